// round 3
// baseline (speedup 1.0000x reference)
#include <cuda_runtime.h>

#define NN      50000
#define DIM     512
#define KMAX    32
#define NTHREADS 256
#define NWARPS  (NTHREADS / 32)

// Per-node completion flags (zero-initialized at load; reset each launch).
__device__ volatile int g_done[NN];

__global__ void reset_kernel() {
    int i = blockIdx.x * blockDim.x + threadIdx.x;
    if (i < NN) g_done[i] = 0;
}

__global__ void __launch_bounds__(NTHREADS, 3)
attn_kernel(const float* __restrict__ feats,
            const float* __restrict__ wq_w,
            const float* __restrict__ wq_b,
            const float* __restrict__ wk_w,
            const float* __restrict__ wk_b,
            const int*   __restrict__ neighbors,
            const int*   __restrict__ deg,
            float*       out)
{
    extern __shared__ float s_rows[];          // KMAX * DIM floats = 64 KB
    __shared__ int   s_nbr[KMAX];
    __shared__ float s_ej[KMAX];
    __shared__ float s_a[KMAX];
    __shared__ float s_red[NWARPS];
    __shared__ float s_ei;

    const int i    = blockIdx.x;
    const int tid  = threadIdx.x;
    const int lane = tid & 31;
    const int warp = tid >> 5;
    const int d    = deg[i];                   // uniform across block

    // ---- Wait for earlier-indexed valid neighbors to be done (acquire) ----
    if (tid < KMAX) {
        int nb = neighbors[i * KMAX + tid];
        s_nbr[tid] = nb;
        if (tid < d && nb < i) {
            while (g_done[nb] == 0) { __nanosleep(64); }
            __threadfence();                   // acquire: order flag before row reads
        }
    }
    __syncthreads();

    // ---- ei partial: dot(feats[i], wq_w) ----
    const float* fi = feats + (size_t)i * DIM;
    {
        float p = 0.f;
        #pragma unroll 2
        for (int j = tid; j < DIM; j += NTHREADS) p += fi[j] * wq_w[j];
        #pragma unroll
        for (int o = 16; o > 0; o >>= 1) p += __shfl_down_sync(0xffffffffu, p, o);
        if (lane == 0) s_red[warp] = p;
    }

    // ---- Gather valid neighbor rows into smem (updated for nb<i, else orig) ----
    for (int k = warp; k < d; k += NWARPS) {
        int nb = s_nbr[k];
        const float4* src = (const float4*)((nb < i ? out : feats) + (size_t)nb * DIM);
        float4* dst = (float4*)(s_rows + k * DIM);
        #pragma unroll
        for (int j = lane; j < DIM / 4; j += 32) dst[j] = src[j];
    }
    __syncthreads();

    // ---- finalize ei; ej_k = dot(row_k, wk_w) + wk_b ----
    if (tid == 0) {
        float e = 0.f;
        #pragma unroll
        for (int w = 0; w < NWARPS; w++) e += s_red[w];
        s_ei = e + wq_b[0];
    }
    const float wkb = wk_b[0];
    for (int k = warp; k < d; k += NWARPS) {
        const float* row = s_rows + k * DIM;
        float p = 0.f;
        #pragma unroll 4
        for (int j = lane; j < DIM; j += 32) p += row[j] * wk_w[j];
        #pragma unroll
        for (int o = 16; o > 0; o >>= 1) p += __shfl_down_sync(0xffffffffu, p, o);
        if (lane == 0) s_ej[k] = p + wkb;
    }
    __syncthreads();

    // ---- masked softmax over the d valid scores (warp 0) ----
    if (warp == 0) {
        const float NEG = -3.4e38f;
        float e = (lane < d) ? s_ei * s_ej[lane] : NEG;
        float m = e;
        #pragma unroll
        for (int o = 16; o > 0; o >>= 1) m = fmaxf(m, __shfl_xor_sync(0xffffffffu, m, o));
        float ex = (lane < d) ? expf(e - m) : 0.f;
        float s = ex;
        #pragma unroll
        for (int o = 16; o > 0; o >>= 1) s += __shfl_xor_sync(0xffffffffu, s, o);
        if (lane < d) s_a[lane] = ex / s;
    }
    __syncthreads();

    // ---- out[i] = feats[i] + sum_k a_k * row_k ----
    float* oi = out + (size_t)i * DIM;
    #pragma unroll 2
    for (int j = tid; j < DIM; j += NTHREADS) {
        float acc = fi[j];
        #pragma unroll 8
        for (int k = 0; k < d; k++) acc = fmaf(s_a[k], s_rows[k * DIM + j], acc);
        oi[j] = acc;
    }
    __syncthreads();

    // ---- release: publish this row ----
    if (tid == 0) {
        __threadfence();
        g_done[i] = 1;
    }
}

extern "C" void kernel_launch(void* const* d_in, const int* in_sizes, int n_in,
                              void* d_out, int out_size) {
    const float* feats     = (const float*)d_in[0];
    const float* wq_w      = (const float*)d_in[1];
    const float* wq_b      = (const float*)d_in[2];
    const float* wk_w      = (const float*)d_in[3];
    const float* wk_b      = (const float*)d_in[4];
    const int*   neighbors = (const int*)d_in[5];
    const int*   deg       = (const int*)d_in[6];
    float*       out       = (float*)d_out;

    static bool attr_set = false;
    if (!attr_set) {
        cudaFuncSetAttribute(attn_kernel,
                             cudaFuncAttributeMaxDynamicSharedMemorySize,
                             KMAX * DIM * (int)sizeof(float));
        attr_set = true;
    }

    reset_kernel<<<(NN + 255) / 256, 256>>>();
    attn_kernel<<<NN, NTHREADS, KMAX * DIM * sizeof(float)>>>(
        feats, wq_w, wq_b, wk_w, wk_b, neighbors, deg, out);
}

// round 4
// speedup vs baseline: 1.6448x; 1.6448x over previous
#include <cuda_runtime.h>

#define NN       50000
#define DIM      512
#define KMAX     32
#define NTHREADS 128

// Per-node completion flags + published updated-row key score.
__device__ int   g_done[NN];
__device__ float g_eknew[NN];
__device__ float g_eq[NN];    // feats[i] . wq_w + wq_b (original rows)
__device__ float g_ek0[NN];   // feats[i] . wk_w + wk_b (original rows)

// One warp per row: compute eq / ek0 for all nodes; also reset flags.
__global__ void pre_kernel(const float* __restrict__ feats,
                           const float* __restrict__ wq_w,
                           const float* __restrict__ wq_b,
                           const float* __restrict__ wk_w,
                           const float* __restrict__ wk_b)
{
    int gtid = blockIdx.x * blockDim.x + threadIdx.x;
    if (gtid < NN) g_done[gtid] = 0;

    int row_i = gtid >> 5;
    int lane  = gtid & 31;
    if (row_i >= NN) return;

    const float4* row = (const float4*)(feats + (size_t)row_i * DIM);
    const float4* q4  = (const float4*)wq_w;
    const float4* k4  = (const float4*)wk_w;
    float sq = 0.f, sk = 0.f;
    #pragma unroll
    for (int j = lane; j < DIM / 4; j += 32) {
        float4 f = row[j];
        float4 q = q4[j];
        float4 k = k4[j];
        sq += f.x*q.x + f.y*q.y + f.z*q.z + f.w*q.w;
        sk += f.x*k.x + f.y*k.y + f.z*k.z + f.w*k.w;
    }
    #pragma unroll
    for (int o = 16; o > 0; o >>= 1) {
        sq += __shfl_down_sync(0xffffffffu, sq, o);
        sk += __shfl_down_sync(0xffffffffu, sk, o);
    }
    if (lane == 0) {
        g_eq[row_i]  = sq + *wq_b;
        g_ek0[row_i] = sk + *wk_b;
    }
}

__global__ void __launch_bounds__(NTHREADS, 12)
attn_kernel(const float* __restrict__ feats,
            const int*   __restrict__ neighbors,
            const int*   __restrict__ deg,
            const float* __restrict__ wk_b,
            float*       out)
{
    __shared__ float        s_a[KMAX];
    __shared__ const float* s_ptr[KMAX];

    const int i   = blockIdx.x;
    const int tid = threadIdx.x;
    const int d   = deg[i];

    float ekn = 0.f;   // meaningful only on tid 0

    // ---- warp 0: waits, scalar scores, softmax, s_a + row pointers ----
    if (tid < KMAX) {
        const bool valid = tid < d;
        float ej = 0.f;
        if (valid) {
            int nb = neighbors[i * KMAX + tid];
            if (nb < i) {
                while (((volatile int*)g_done)[nb] == 0) { __nanosleep(40); }
                __threadfence();                       // acquire
                ej = ((volatile float*)g_eknew)[nb];
            } else {
                ej = g_ek0[nb];
            }
            s_ptr[tid] = (nb < i ? out : feats) + (size_t)nb * DIM;
        }
        const float wkb = *wk_b;
        const float ei  = g_eq[i];

        float e = valid ? ei * ej : -3.4e38f;
        float m = e;
        #pragma unroll
        for (int o = 16; o > 0; o >>= 1)
            m = fmaxf(m, __shfl_xor_sync(0xffffffffu, m, o));
        float ex  = valid ? expf(e - m) : 0.f;
        float s   = ex;
        float num = ex * (ej - wkb);
        #pragma unroll
        for (int o = 16; o > 0; o >>= 1) {
            s   += __shfl_xor_sync(0xffffffffu, s, o);
            num += __shfl_xor_sync(0xffffffffu, num, o);
        }
        if (valid) s_a[tid] = ex / s;
        if (tid == 0)
            ekn = g_ek0[i] + ((d > 0) ? num / s : 0.f);
    }
    __syncthreads();

    // ---- out[i] = feats[i] + sum_k a_k * row_k (rows straight from L2) ----
    const float* fi = feats + (size_t)i * DIM;
    float acc0 = fi[tid];
    float acc1 = fi[tid + 128];
    float acc2 = fi[tid + 256];
    float acc3 = fi[tid + 384];

    #pragma unroll 4
    for (int k = 0; k < d; k++) {
        const float  a = s_a[k];
        const float* r = s_ptr[k];
        acc0 = fmaf(a, r[tid],       acc0);
        acc1 = fmaf(a, r[tid + 128], acc1);
        acc2 = fmaf(a, r[tid + 256], acc2);
        acc3 = fmaf(a, r[tid + 384], acc3);
    }

    float* oi = out + (size_t)i * DIM;
    oi[tid]       = acc0;
    oi[tid + 128] = acc1;
    oi[tid + 256] = acc2;
    oi[tid + 384] = acc3;
    __syncthreads();

    // ---- release: rows visible -> publish score -> publish flag ----
    if (tid == 0) {
        __threadfence();
        ((volatile float*)g_eknew)[i] = ekn;
        __threadfence();
        ((volatile int*)g_done)[i] = 1;
    }
}

extern "C" void kernel_launch(void* const* d_in, const int* in_sizes, int n_in,
                              void* d_out, int out_size) {
    const float* feats     = (const float*)d_in[0];
    const float* wq_w      = (const float*)d_in[1];
    const float* wq_b      = (const float*)d_in[2];
    const float* wk_w      = (const float*)d_in[3];
    const float* wk_b      = (const float*)d_in[4];
    const int*   neighbors = (const int*)d_in[5];
    const int*   deg       = (const int*)d_in[6];
    float*       out       = (float*)d_out;

    // NN warps for the GEMV + flag reset: NN*32 threads / 256 = 6250 blocks
    pre_kernel<<<(NN * 32 + 255) / 256, 256>>>(feats, wq_w, wq_b, wk_w, wk_b);
    attn_kernel<<<NN, NTHREADS>>>(feats, neighbors, deg, wk_b, out);
}

// round 6
// speedup vs baseline: 2.5791x; 1.5681x over previous
#include <cuda_runtime.h>

#define NN       50000
#define DIM      512
#define KMAX     32
#define NTHREADS 128

// Score chain: packed word per node  [63:32]=float eknew bits, [31:0]=ready flag.
__device__ unsigned long long g_score[NN];
// Row chain: out[i] row fully written.
__device__ int   g_rowdone[NN];
__device__ float g_eq[NN];    // feats[i].wq_w + wq_b
__device__ float g_ek0[NN];   // feats[i].wk_w + wk_b

__device__ __forceinline__ unsigned long long ld_relaxed_u64(const unsigned long long* p) {
    unsigned long long v;
    asm volatile("ld.global.relaxed.gpu.b64 %0, [%1];" : "=l"(v) : "l"(p) : "memory");
    return v;
}
__device__ __forceinline__ void st_relaxed_u64(unsigned long long* p, unsigned long long v) {
    asm volatile("st.global.relaxed.gpu.b64 [%0], %1;" :: "l"(p), "l"(v) : "memory");
}
__device__ __forceinline__ int ld_acquire_i32(const int* p) {
    int v;
    asm volatile("ld.global.acquire.gpu.b32 %0, [%1];" : "=r"(v) : "l"(p) : "memory");
    return v;
}
__device__ __forceinline__ void st_release_i32(int* p, int v) {
    asm volatile("st.global.release.gpu.b32 [%0], %1;" :: "l"(p), "r"(v) : "memory");
}

// One warp per row: eq/ek0 GEMV for all nodes; also reset both flag arrays.
__global__ void pre_kernel(const float* __restrict__ feats,
                           const float* __restrict__ wq_w,
                           const float* __restrict__ wq_b,
                           const float* __restrict__ wk_w,
                           const float* __restrict__ wk_b)
{
    int gtid = blockIdx.x * blockDim.x + threadIdx.x;
    if (gtid < NN) { g_score[gtid] = 0ull; g_rowdone[gtid] = 0; }

    int row_i = gtid >> 5;
    int lane  = gtid & 31;
    if (row_i >= NN) return;

    const float4* row = (const float4*)(feats + (size_t)row_i * DIM);
    const float4* q4  = (const float4*)wq_w;
    const float4* k4  = (const float4*)wk_w;
    float sq = 0.f, sk = 0.f;
    #pragma unroll
    for (int j = lane; j < DIM / 4; j += 32) {
        float4 f = row[j];
        float4 q = q4[j];
        float4 k = k4[j];
        sq += f.x*q.x + f.y*q.y + f.z*q.z + f.w*q.w;
        sk += f.x*k.x + f.y*k.y + f.z*k.z + f.w*k.w;
    }
    #pragma unroll
    for (int o = 16; o > 0; o >>= 1) {
        sq += __shfl_down_sync(0xffffffffu, sq, o);
        sk += __shfl_down_sync(0xffffffffu, sk, o);
    }
    if (lane == 0) {
        g_eq[row_i]  = sq + *wq_b;
        g_ek0[row_i] = sk + *wk_b;
    }
}

__global__ void __launch_bounds__(NTHREADS, 12)
attn_kernel(const float* __restrict__ feats,
            const int*   __restrict__ neighbors,
            const int*   __restrict__ deg,
            const float* __restrict__ wk_b,
            float*       out)
{
    __shared__ float        s_a[KMAX];
    __shared__ const float* s_ptr[KMAX];

    const int i   = blockIdx.x;
    const int tid = threadIdx.x;
    const int d   = deg[i];

    // ---- prefetch center row early (independent of all waits) ----
    const float* fi = feats + (size_t)i * DIM;
    float acc0 = fi[tid];
    float acc1 = fi[tid + 128];
    float acc2 = fi[tid + 256];
    float acc3 = fi[tid + 384];

    if (tid < KMAX) {
        const bool valid = tid < d;
        int  nb    = 0;
        bool early = false;
        float ej   = 0.f;
        if (valid) {
            nb    = neighbors[i * KMAX + tid];
            early = nb < i;
            s_ptr[tid] = (early ? out : feats) + (size_t)nb * DIM;
            if (early) {
                // --- score chain wait: payload packed in the flag word ---
                unsigned long long w;
                int it = 0;
                while ((unsigned)((w = ld_relaxed_u64(&g_score[nb]))) == 0u) {
                    if (++it > 8) __nanosleep(20);
                }
                ej = __uint_as_float((unsigned)(w >> 32));
            } else {
                ej = g_ek0[nb];
            }
        }

        // ---- softmax over valid scores (whole warp participates) ----
        const float wkb = *wk_b;
        const float ei  = g_eq[i];
        float e = valid ? ei * ej : -3.4e38f;
        float m = e;
        #pragma unroll
        for (int o = 16; o > 0; o >>= 1)
            m = fmaxf(m, __shfl_xor_sync(0xffffffffu, m, o));
        float ex  = valid ? expf(e - m) : 0.f;
        float s   = ex;
        float num = ex * (ej - wkb);
        #pragma unroll
        for (int o = 16; o > 0; o >>= 1) {
            s   += __shfl_xor_sync(0xffffffffu, s, o);
            num += __shfl_xor_sync(0xffffffffu, num, o);
        }
        if (valid) s_a[tid] = ex / s;

        // ---- publish score IMMEDIATELY (before the row pass) ----
        if (tid == 0) {
            float ekn = g_ek0[i] + ((d > 0) ? num / s : 0.f);
            unsigned long long w =
                ((unsigned long long)__float_as_uint(ekn) << 32) | 1ull;
            st_relaxed_u64(&g_score[i], w);
        }

        // ---- row chain wait (only now; softmax already done) ----
        if (valid && early) {
            int it = 0;
            while (ld_acquire_i32(&g_rowdone[nb]) == 0) {
                if (++it > 8) __nanosleep(20);
            }
        }
    }
    __syncthreads();

    // ---- out[i] = feats[i] + sum_k a_k * row_k ----
    #pragma unroll 4
    for (int k = 0; k < d; k++) {
        const float  a = s_a[k];
        const float* r = s_ptr[k];
        acc0 = fmaf(a, r[tid],       acc0);
        acc1 = fmaf(a, r[tid + 128], acc1);
        acc2 = fmaf(a, r[tid + 256], acc2);
        acc3 = fmaf(a, r[tid + 384], acc3);
    }

    float* oi = out + (size_t)i * DIM;
    oi[tid]       = acc0;
    oi[tid + 128] = acc1;
    oi[tid + 256] = acc2;
    oi[tid + 384] = acc3;
    __syncthreads();

    // ---- release: row visible ----
    if (tid == 0) st_release_i32(&g_rowdone[i], 1);
}

extern "C" void kernel_launch(void* const* d_in, const int* in_sizes, int n_in,
                              void* d_out, int out_size) {
    const float* feats     = (const float*)d_in[0];
    const float* wq_w      = (const float*)d_in[1];
    const float* wq_b      = (const float*)d_in[2];
    const float* wk_w      = (const float*)d_in[3];
    const float* wk_b      = (const float*)d_in[4];
    const int*   neighbors = (const int*)d_in[5];
    const int*   deg       = (const int*)d_in[6];
    float*       out       = (float*)d_out;

    pre_kernel<<<(NN * 32 + 255) / 256, 256>>>(feats, wq_w, wq_b, wk_w, wk_b);
    attn_kernel<<<NN, NTHREADS>>>(feats, neighbors, deg, wk_b, out);
}